// round 11
// baseline (speedup 1.0000x reference)
#include <cuda_runtime.h>
#include <cuda_bf16.h>
#include <cuda_fp16.h>
#include <cstdint>

#define B_      512
#define GFS_    512
#define NATOMS_ 128
#define KATT_   256
#define NUNITS  (B_ * 2)

// ---------------- scratch (no cudaMalloc allowed) ----------------
__device__ float g_mgate[B_ * KATT_];
__device__ float g_M0[B_ * GFS_];
__device__ __half g_w16[2][KATT_ * GFS_];                    // W fp16
__device__ __half g_X16[2][(size_t)B_ * GFS_ * NATOMS_];     // X fp16, [b][f][n]

// ---------------- helpers ----------------
__device__ __forceinline__ uint32_t smem_u32(const void* p) {
    uint32_t a;
    asm("{ .reg .u64 t; cvta.to.shared.u64 t, %1; cvt.u32.u64 %0, t; }" : "=r"(a) : "l"(p));
    return a;
}
__device__ __forceinline__ uint32_t sw128(uint32_t off) { return off ^ ((off >> 3) & 0x70); }

__device__ __forceinline__ void ldsm_x4(uint32_t* r, uint32_t addr) {
    asm volatile("ldmatrix.sync.aligned.m8n8.x4.shared.b16 {%0,%1,%2,%3}, [%4];"
                 : "=r"(r[0]), "=r"(r[1]), "=r"(r[2]), "=r"(r[3]) : "r"(addr));
}
__device__ __forceinline__ void ldsm_x4t(uint32_t* r, uint32_t addr) {
    asm volatile("ldmatrix.sync.aligned.m8n8.x4.trans.shared.b16 {%0,%1,%2,%3}, [%4];"
                 : "=r"(r[0]), "=r"(r[1]), "=r"(r[2]), "=r"(r[3]) : "r"(addr));
}
__device__ __forceinline__ void mma_f16(float* c, const uint32_t* a, const uint32_t* b) {
    asm volatile("mma.sync.aligned.m16n8k16.row.col.f32.f16.f16.f32 "
                 "{%0,%1,%2,%3}, {%4,%5,%6,%7}, {%8,%9}, {%0,%1,%2,%3};"
                 : "+f"(c[0]), "+f"(c[1]), "+f"(c[2]), "+f"(c[3])
                 : "r"(a[0]), "r"(a[1]), "r"(a[2]), "r"(a[3]), "r"(b[0]), "r"(b[1]));
}
__device__ __forceinline__ void cp16(uint32_t saddr, const void* gaddr) {
    asm volatile("cp.async.cg.shared.global [%0], [%1], 16;" :: "r"(saddr), "l"(gaddr));
}
#define CP_COMMIT() asm volatile("cp.async.commit_group;" ::: "memory")
#define CP_WAIT2()  asm volatile("cp.async.wait_group 2;" ::: "memory")

// HW tanh (MUFU), rel err ~2^-11
__device__ __forceinline__ float htanh(float x) {
    float y;
    asm("tanh.approx.f32 %0, %1;" : "=f"(y) : "f"(x));
    return y;
}

// ---------------- precise rational tanh (gate path; |err| ~1e-7) ----------------
__device__ __forceinline__ float rtanh(float x) {
    float xc = fminf(fmaxf(x, -7.9053111f), 7.9053111f);
    float s = xc * xc;
    float p = -2.76076847742355e-16f;
    p = fmaf(p, s,  2.00018790482477e-13f);
    p = fmaf(p, s, -8.60467152213735e-11f);
    p = fmaf(p, s,  5.12229709037114e-08f);
    p = fmaf(p, s,  1.48572235717979e-05f);
    p = fmaf(p, s,  6.37261928875436e-04f);
    p = fmaf(p, s,  4.89352455891786e-03f);
    p = p * xc;
    float q = 1.19825839466702e-06f;
    q = fmaf(q, s, 1.18534705686654e-04f);
    q = fmaf(q, s, 2.26843463243900e-03f);
    q = fmaf(q, s, 4.89352518554385e-03f);
    return __fdividef(p, q);
}

// ---------------- P0: W -> fp16 ----------------
__global__ __launch_bounds__(1024) void prep_kernel(const float* __restrict__ Wv,
                                                    const float* __restrict__ Wq)
{
    int id = blockIdx.x * 1024 + threadIdx.x;
    int src = id >> 17;
    int e   = id & 131071;
    g_w16[src][e] = __float2half_rn((src ? Wq : Wv)[e]);
}

// ---------------- K1a: rowsums -> M0; also write X fp16 copy ----------------
__global__ __launch_bounds__(256) void m0_kernel(const float* __restrict__ V,
                                                 const float* __restrict__ Q)
{
    int b    = blockIdx.x >> 2;
    int part = blockIdx.x & 3;
    int lane = threadIdx.x & 31;
    int warp = threadIdx.x >> 5;

    for (int i = 0; i < 16; i++) {
        int f = part * 128 + warp * 16 + i;
        size_t base = ((size_t)b * GFS_ + f) * NATOMS_;
        float4 v = __ldcs((const float4*)(V + base + lane * 4));
        float4 q = __ldcs((const float4*)(Q + base + lane * 4));

        __half2 vh0 = __floats2half2_rn(v.x, v.y);
        __half2 vh1 = __floats2half2_rn(v.z, v.w);
        __half2 qh0 = __floats2half2_rn(q.x, q.y);
        __half2 qh1 = __floats2half2_rn(q.z, q.w);
        uint2 vu = { *(uint32_t*)&vh0, *(uint32_t*)&vh1 };
        uint2 qu = { *(uint32_t*)&qh0, *(uint32_t*)&qh1 };
        *(uint2*)(&g_X16[0][base + lane * 4]) = vu;
        *(uint2*)(&g_X16[1][base + lane * 4]) = qu;

        float sv = v.x + v.y + v.z + v.w;
        float sq = q.x + q.y + q.z + q.w;
        #pragma unroll
        for (int off = 16; off; off >>= 1) {
            sv += __shfl_xor_sync(0xffffffffu, sv, off);
            sq += __shfl_xor_sync(0xffffffffu, sq, off);
        }
        if (lane == 0)
            g_M0[b * GFS_ + f] = rtanh(sv * (1.0f / 64.0f)) * rtanh(sq * (1.0f / 64.0f));
    }
}

// ---------------- K1b: m_gate = tanh(Wm @ M0), 4 batches per CTA ----------------
__global__ __launch_bounds__(256) void gate_kernel(const float* __restrict__ Wm)
{
    __shared__ __align__(16) float M0s[4][GFS_];
    int b0  = blockIdx.x * 4;
    int tid = threadIdx.x;

    for (int i = tid; i < 4 * GFS_ / 4; i += 256)
        ((float4*)&M0s[0][0])[i] = ((const float4*)(g_M0 + b0 * GFS_))[i];
    __syncthreads();

    int k = tid;
    const float4* wr = (const float4*)(Wm + (size_t)k * GFS_);
    float acc0 = 0.f, acc1 = 0.f, acc2 = 0.f, acc3 = 0.f;
    #pragma unroll 4
    for (int i = 0; i < GFS_ / 4; i++) {
        float4 w = wr[i];
        float4 m0 = ((const float4*)M0s[0])[i];
        float4 m1 = ((const float4*)M0s[1])[i];
        float4 m2 = ((const float4*)M0s[2])[i];
        float4 m3 = ((const float4*)M0s[3])[i];
        acc0 = fmaf(w.x, m0.x, fmaf(w.y, m0.y, fmaf(w.z, m0.z, fmaf(w.w, m0.w, acc0))));
        acc1 = fmaf(w.x, m1.x, fmaf(w.y, m1.y, fmaf(w.z, m1.z, fmaf(w.w, m1.w, acc1))));
        acc2 = fmaf(w.x, m2.x, fmaf(w.y, m2.y, fmaf(w.z, m2.z, fmaf(w.w, m2.w, acc2))));
        acc3 = fmaf(w.x, m3.x, fmaf(w.y, m3.y, fmaf(w.z, m3.z, fmaf(w.w, m3.w, acc3))));
    }
    g_mgate[(b0 + 0) * KATT_ + k] = rtanh(acc0);
    g_mgate[(b0 + 1) * KATT_ + k] = rtanh(acc1);
    g_mgate[(b0 + 2) * KATT_ + k] = rtanh(acc2);
    g_mgate[(b0 + 3) * KATT_ + k] = rtanh(acc3);
}

// ---------------- K2: persistent mma.sync, 256 thr, 64x64 warp tiles ----------------
#define A_OFF       0
#define B_OFF       32768
#define STAGE_BYTES 49152
#define NSTAGE      4
#define WHG_OFF     196608
#define PART_OFF    197632
#define ALPHA_OFF   199680
#define SMEM_TOTAL  200704

// A chunk [256 m][64 f] fp16 SW128 (rows 128B)
__device__ __forceinline__ void fillA(uint32_t stage, const __half* Wc)
{
    int tid = threadIdx.x;
    #pragma unroll
    for (int it = 0; it < 8; it++) {
        int idx = it * 256 + tid;          // 0..2047
        int m   = idx >> 3;
        int u   = idx & 7;
        cp16(stage + A_OFF + sw128((uint32_t)(m * 128 + u * 16)),
             Wc + (size_t)m * GFS_ + u * 8);
    }
}

// B chunk [64 k(f)][128 n] fp16, rows 256B, 16B-unit XOR by (k&7)
__device__ __forceinline__ void fillB(uint32_t stage, const __half* Xc)
{
    int tid = threadIdx.x;
    #pragma unroll
    for (int it = 0; it < 4; it++) {
        int idx = it * 256 + tid;          // 0..1023
        int k   = idx >> 4;
        int u   = idx & 15;
        cp16(stage + B_OFF + (uint32_t)(k * 256 + ((u << 4) ^ ((k & 7) << 4))),
             Xc + (size_t)k * NATOMS_ + u * 8);
    }
}

__global__ void __launch_bounds__(256, 1)
main_kernel(const float* __restrict__ Wh, float* __restrict__ out)
{
    extern __shared__ char sm[];
    uint32_t sb = smem_u32(sm);

    int tid  = threadIdx.x;
    int wid  = tid >> 5;        // 0..7
    int lane = tid & 31;
    int grid = gridDim.x;       // even

    float* whg   = (float*)(sm + WHG_OFF);
    float* part  = (float*)(sm + PART_OFF);
    float* alpha = (float*)(sm + ALPHA_OFF);

    // warp tile: 64m x 64n; warp grid 4(m) x 2(n)
    int wm = wid >> 1;
    int wn = wid & 1;

    uint32_t aRow = (uint32_t)((wm * 64 + (lane & 15)) * 128);
    uint32_t aCol = (uint32_t)((lane >> 4) * 16);
    int q = lane >> 3;
    int r = lane & 7;
    uint32_t bKpart = (uint32_t)((q & 1) * 8 + r);
    uint32_t bUpart = (uint32_t)(wn * 8 + (q >> 1));   // 16B-unit base (+ jj*2)

    int src = blockIdx.x & 1;
    const __half* W16 = g_w16[src];
    const size_t unitStride = (size_t)(grid >> 1) * GFS_ * NATOMS_;

    uint32_t stg[NSTAGE] = { sb, sb + STAGE_BYTES, sb + 2 * STAGE_BYTES, sb + 3 * STAGE_BYTES };
    int sc = 0;

    const __half* Xrow = g_X16[src] + (size_t)(blockIdx.x >> 1) * GFS_ * NATOMS_;

    // prologue: chunks 0,1,2 of first unit
    fillA(stg[0], W16);       fillB(stg[0], Xrow);                          CP_COMMIT();
    fillA(stg[1], W16 + 64);  fillB(stg[1], Xrow + (size_t)64  * NATOMS_);  CP_COMMIT();
    fillA(stg[2], W16 + 128); fillB(stg[2], Xrow + (size_t)128 * NATOMS_);  CP_COMMIT();

    #pragma unroll 1
    for (int u = blockIdx.x; u < NUNITS; u += grid) {
        int b = u >> 1;
        const __half* Xnext = (u + grid < NUNITS) ? Xrow + unitStride : Xrow;

        if (tid < KATT_) whg[tid] = Wh[tid] * g_mgate[b * KATT_ + tid];

        float acc[4][8][4];
        #pragma unroll
        for (int i = 0; i < 4; i++)
            #pragma unroll
            for (int j = 0; j < 8; j++)
                #pragma unroll
                for (int e = 0; e < 4; e++) acc[i][j][e] = 0.0f;

        #pragma unroll 1
        for (int lc = 0; lc < 8; lc++) {
            CP_WAIT2();                 // own copies for chunk lc done (≤2 groups in flight)
            __syncthreads();            // block-wide visibility; orders consume(lc-1) before refill

            uint32_t aB = stg[sc] + A_OFF;
            uint32_t bB = stg[sc] + B_OFF;
            sc++; if (sc == NSTAGE) sc = 0;

            // consume chunk lc: fragment double-buffered k-loop (8 LDSM -> 32 MMA per ks)
            uint32_t af[2][16], bf[2][16];
            {   // load ks=0 fragments
                #pragma unroll
                for (int i = 0; i < 4; i++)
                    ldsm_x4(&af[0][i * 4], aB + sw128(aRow + i * 2048 + aCol));
                #pragma unroll
                for (int jj = 0; jj < 4; jj++) {
                    uint32_t kRow = bKpart;
                    uint32_t un   = bUpart + jj * 2;
                    ldsm_x4t(&bf[0][jj * 4], bB + kRow * 256 + ((un * 16) ^ ((kRow & 7) * 16)));
                }
            }
            #pragma unroll
            for (int ks = 0; ks < 4; ks++) {
                int cur = ks & 1;
                if (ks < 3) {
                    int nxt = cur ^ 1;
                    uint32_t kOff = (uint32_t)((ks + 1) * 32);
                    #pragma unroll
                    for (int i = 0; i < 4; i++)
                        ldsm_x4(&af[nxt][i * 4], aB + sw128(aRow + i * 2048 + kOff + aCol));
                    uint32_t kRow = (uint32_t)((ks + 1) * 16) + bKpart;
                    #pragma unroll
                    for (int jj = 0; jj < 4; jj++) {
                        uint32_t un = bUpart + jj * 2;
                        ldsm_x4t(&bf[nxt][jj * 4], bB + kRow * 256 + ((un * 16) ^ ((kRow & 7) * 16)));
                    }
                }
                #pragma unroll
                for (int i = 0; i < 4; i++)
                    #pragma unroll
                    for (int j = 0; j < 8; j++)
                        mma_f16(acc[i][j], &af[cur][i * 4], &bf[cur][j * 2]);
            }

            // refill ring slot (sc-1+3)%4 == stage of chunk lc+3 (this or next unit)
            // WAR-safe: that stage's consume (iter lc-1) is ordered before this iter's sync
            {
                int fs = sc + 2; if (fs >= NSTAGE) fs -= NSTAGE;   // (old sc)+3
                int fc = lc + 3;
                const __half* Xf = (fc < 8) ? Xrow : Xnext;
                int f0 = (fc & 7) * 64;
                fillA(stg[fs], W16 + f0);
                fillB(stg[fs], Xf + (size_t)f0 * NATOMS_);
                CP_COMMIT();
            }
        }

        // ---- epilogue (next unit's chunks are in flight) ----
        float p[8][2];
        #pragma unroll
        for (int j = 0; j < 8; j++) { p[j][0] = 0.f; p[j][1] = 0.f; }

        int m0r = wm * 64 + (lane >> 2);
        #pragma unroll
        for (int i = 0; i < 4; i++) {
            float w0 = whg[m0r + i * 16];
            float w1 = whg[m0r + i * 16 + 8];
            #pragma unroll
            for (int j = 0; j < 8; j++) {
                p[j][0] = fmaf(w0, htanh(acc[i][j][0]), p[j][0]);
                p[j][1] = fmaf(w0, htanh(acc[i][j][1]), p[j][1]);
                p[j][0] = fmaf(w1, htanh(acc[i][j][2]), p[j][0]);
                p[j][1] = fmaf(w1, htanh(acc[i][j][3]), p[j][1]);
            }
        }
        #pragma unroll
        for (int off = 4; off <= 16; off <<= 1)
            #pragma unroll
            for (int j = 0; j < 8; j++) {
                p[j][0] += __shfl_xor_sync(0xffffffffu, p[j][0], off);
                p[j][1] += __shfl_xor_sync(0xffffffffu, p[j][1], off);
            }
        if (lane < 4) {
            #pragma unroll
            for (int j = 0; j < 8; j++) {
                int col = wn * 64 + j * 8 + lane * 2;
                part[wm * 128 + col]     = p[j][0];
                part[wm * 128 + col + 1] = p[j][1];
            }
        }
        __syncthreads();

        // ---- 2-sync softmax: every warp redundantly reduces all 128 logits ----
        {
            float s[4];
            #pragma unroll
            for (int k = 0; k < 4; k++) {
                int n = lane + 32 * k;
                s[k] = part[n] + part[128 + n] + part[256 + n] + part[384 + n];
            }
            float mx = fmaxf(fmaxf(s[0], s[1]), fmaxf(s[2], s[3]));
            #pragma unroll
            for (int off = 16; off; off >>= 1)
                mx = fmaxf(mx, __shfl_xor_sync(0xffffffffu, mx, off));
            float e[4], sum = 0.f;
            #pragma unroll
            for (int k = 0; k < 4; k++) { e[k] = __expf(s[k] - mx); sum += e[k]; }
            #pragma unroll
            for (int off = 16; off; off >>= 1)
                sum += __shfl_xor_sync(0xffffffffu, sum, off);
            float rs = 1.0f / sum;
            if (wid == 0) {
                #pragma unroll
                for (int k = 0; k < 4; k++) {
                    int n = lane + 32 * k;
                    float a = e[k] * rs;
                    alpha[n] = a;
                    out[2 * B_ * GFS_ + src * B_ * NATOMS_ + b * NATOMS_ + n] = a;
                }
            }
        }
        __syncthreads();

        // ---- vector[f] = sum_n alpha[n] * X16[f][n]  (L2-hot), 2 f per thread ----
        #pragma unroll
        for (int rep = 0; rep < 2; rep++) {
            int f = tid + rep * 256;
            const uint4* xr = (const uint4*)(Xrow + (size_t)f * NATOMS_);
            float a = 0.0f;
            #pragma unroll
            for (int i = 0; i < 16; i++) {
                uint4 uu = xr[i];
                const float* al = alpha + i * 8;
                float2 p0 = __half22float2(*(const __half2*)&uu.x);
                float2 p1 = __half22float2(*(const __half2*)&uu.y);
                float2 p2 = __half22float2(*(const __half2*)&uu.z);
                float2 p3 = __half22float2(*(const __half2*)&uu.w);
                a = fmaf(p0.x, al[0], a); a = fmaf(p0.y, al[1], a);
                a = fmaf(p1.x, al[2], a); a = fmaf(p1.y, al[3], a);
                a = fmaf(p2.x, al[4], a); a = fmaf(p2.y, al[5], a);
                a = fmaf(p3.x, al[6], a); a = fmaf(p3.y, al[7], a);
            }
            out[src * B_ * GFS_ + b * GFS_ + f] = a;
        }
        __syncthreads();   // alpha/whg/part WAR guard before next unit writes them

        Xrow = Xnext;
    }
}

// ---------------- launch ----------------
extern "C" void kernel_launch(void* const* d_in, const int* in_sizes, int n_in,
                              void* d_out, int out_size)
{
    const float* V  = (const float*)d_in[0];
    const float* Q  = (const float*)d_in[1];
    const float* Wm = (const float*)d_in[2];
    const float* Wv = (const float*)d_in[3];
    const float* Wq = (const float*)d_in[4];
    const float* Wh = (const float*)d_in[5];
    float* out = (float*)d_out;

    cudaFuncSetAttribute(main_kernel, cudaFuncAttributeMaxDynamicSharedMemorySize, SMEM_TOTAL);

    int sms = 148;
    cudaDeviceGetAttribute(&sms, cudaDevAttrMultiProcessorCount, 0);
    if (sms < 1 || sms > NUNITS) sms = 148;
    sms &= ~1;   // even grid so unit parity (src) is fixed per CTA

    prep_kernel<<<256, 1024>>>(Wv, Wq);
    m0_kernel<<<B_ * 4, 256>>>(V, Q);
    gate_kernel<<<B_ / 4, 256>>>(Wm);
    main_kernel<<<sms, 256, SMEM_TOTAL>>>(Wh, out);
}

// round 12
// speedup vs baseline: 1.0170x; 1.0170x over previous
#include <cuda_runtime.h>
#include <cuda_bf16.h>
#include <cuda_fp16.h>
#include <cstdint>

#define B_      512
#define GFS_    512
#define NATOMS_ 128
#define KATT_   256
#define NUNITS  (B_ * 2)

// ---------------- scratch (no cudaMalloc allowed) ----------------
__device__ float g_mgate[B_ * KATT_];
__device__ float g_M0[B_ * GFS_];
__device__ float g_spart[NUNITS][2][NATOMS_];                // partial logits per k-half
__device__ __half g_w16[2][KATT_ * GFS_];                    // W fp16
__device__ __half g_X16[2][(size_t)B_ * GFS_ * NATOMS_];     // X fp16, [b][f][n]

// ---------------- helpers ----------------
__device__ __forceinline__ uint32_t smem_u32(const void* p) {
    uint32_t a;
    asm("{ .reg .u64 t; cvta.to.shared.u64 t, %1; cvt.u32.u64 %0, t; }" : "=r"(a) : "l"(p));
    return a;
}
__device__ __forceinline__ uint32_t sw128(uint32_t off) { return off ^ ((off >> 3) & 0x70); }

__device__ __forceinline__ void ldsm_x4(uint32_t* r, uint32_t addr) {
    asm volatile("ldmatrix.sync.aligned.m8n8.x4.shared.b16 {%0,%1,%2,%3}, [%4];"
                 : "=r"(r[0]), "=r"(r[1]), "=r"(r[2]), "=r"(r[3]) : "r"(addr));
}
__device__ __forceinline__ void ldsm_x4t(uint32_t* r, uint32_t addr) {
    asm volatile("ldmatrix.sync.aligned.m8n8.x4.trans.shared.b16 {%0,%1,%2,%3}, [%4];"
                 : "=r"(r[0]), "=r"(r[1]), "=r"(r[2]), "=r"(r[3]) : "r"(addr));
}
__device__ __forceinline__ void mma_f16(float* c, const uint32_t* a, const uint32_t* b) {
    asm volatile("mma.sync.aligned.m16n8k16.row.col.f32.f16.f16.f32 "
                 "{%0,%1,%2,%3}, {%4,%5,%6,%7}, {%8,%9}, {%0,%1,%2,%3};"
                 : "+f"(c[0]), "+f"(c[1]), "+f"(c[2]), "+f"(c[3])
                 : "r"(a[0]), "r"(a[1]), "r"(a[2]), "r"(a[3]), "r"(b[0]), "r"(b[1]));
}
__device__ __forceinline__ void cp16(uint32_t saddr, const void* gaddr) {
    asm volatile("cp.async.cg.shared.global [%0], [%1], 16;" :: "r"(saddr), "l"(gaddr));
}
#define CP_COMMIT() asm volatile("cp.async.commit_group;" ::: "memory")
#define CP_WAIT0()  asm volatile("cp.async.wait_group 0;" ::: "memory")
#define CP_WAIT1()  asm volatile("cp.async.wait_group 1;" ::: "memory")
#define CP_WAIT2()  asm volatile("cp.async.wait_group 2;" ::: "memory")

// HW tanh (MUFU), rel err ~2^-11
__device__ __forceinline__ float htanh(float x) {
    float y;
    asm("tanh.approx.f32 %0, %1;" : "=f"(y) : "f"(x));
    return y;
}

// ---------------- precise rational tanh (gate path; |err| ~1e-7) ----------------
__device__ __forceinline__ float rtanh(float x) {
    float xc = fminf(fmaxf(x, -7.9053111f), 7.9053111f);
    float s = xc * xc;
    float p = -2.76076847742355e-16f;
    p = fmaf(p, s,  2.00018790482477e-13f);
    p = fmaf(p, s, -8.60467152213735e-11f);
    p = fmaf(p, s,  5.12229709037114e-08f);
    p = fmaf(p, s,  1.48572235717979e-05f);
    p = fmaf(p, s,  6.37261928875436e-04f);
    p = fmaf(p, s,  4.89352455891786e-03f);
    p = p * xc;
    float q = 1.19825839466702e-06f;
    q = fmaf(q, s, 1.18534705686654e-04f);
    q = fmaf(q, s, 2.26843463243900e-03f);
    q = fmaf(q, s, 4.89352518554385e-03f);
    return __fdividef(p, q);
}

// ---------------- P0: W -> fp16 ----------------
__global__ __launch_bounds__(1024) void prep_kernel(const float* __restrict__ Wv,
                                                    const float* __restrict__ Wq)
{
    int id = blockIdx.x * 1024 + threadIdx.x;
    int src = id >> 17;
    int e   = id & 131071;
    g_w16[src][e] = __float2half_rn((src ? Wq : Wv)[e]);
}

// ---------------- K1a: rowsums -> M0; also write X fp16 copy ----------------
__global__ __launch_bounds__(256) void m0_kernel(const float* __restrict__ V,
                                                 const float* __restrict__ Q)
{
    int b    = blockIdx.x >> 2;
    int part = blockIdx.x & 3;
    int lane = threadIdx.x & 31;
    int warp = threadIdx.x >> 5;

    for (int i = 0; i < 16; i++) {
        int f = part * 128 + warp * 16 + i;
        size_t base = ((size_t)b * GFS_ + f) * NATOMS_;
        float4 v = __ldcs((const float4*)(V + base + lane * 4));
        float4 q = __ldcs((const float4*)(Q + base + lane * 4));

        __half2 vh0 = __floats2half2_rn(v.x, v.y);
        __half2 vh1 = __floats2half2_rn(v.z, v.w);
        __half2 qh0 = __floats2half2_rn(q.x, q.y);
        __half2 qh1 = __floats2half2_rn(q.z, q.w);
        uint2 vu = { *(uint32_t*)&vh0, *(uint32_t*)&vh1 };
        uint2 qu = { *(uint32_t*)&qh0, *(uint32_t*)&qh1 };
        *(uint2*)(&g_X16[0][base + lane * 4]) = vu;
        *(uint2*)(&g_X16[1][base + lane * 4]) = qu;

        float sv = v.x + v.y + v.z + v.w;
        float sq = q.x + q.y + q.z + q.w;
        #pragma unroll
        for (int off = 16; off; off >>= 1) {
            sv += __shfl_xor_sync(0xffffffffu, sv, off);
            sq += __shfl_xor_sync(0xffffffffu, sq, off);
        }
        if (lane == 0)
            g_M0[b * GFS_ + f] = rtanh(sv * (1.0f / 64.0f)) * rtanh(sq * (1.0f / 64.0f));
    }
}

// ---------------- K1b: m_gate = tanh(Wm @ M0), 4 batches per CTA ----------------
__global__ __launch_bounds__(256) void gate_kernel(const float* __restrict__ Wm)
{
    __shared__ __align__(16) float M0s[4][GFS_];
    int b0  = blockIdx.x * 4;
    int tid = threadIdx.x;

    for (int i = tid; i < 4 * GFS_ / 4; i += 256)
        ((float4*)&M0s[0][0])[i] = ((const float4*)(g_M0 + b0 * GFS_))[i];
    __syncthreads();

    int k = tid;
    const float4* wr = (const float4*)(Wm + (size_t)k * GFS_);
    float acc0 = 0.f, acc1 = 0.f, acc2 = 0.f, acc3 = 0.f;
    #pragma unroll 4
    for (int i = 0; i < GFS_ / 4; i++) {
        float4 w = wr[i];
        float4 m0 = ((const float4*)M0s[0])[i];
        float4 m1 = ((const float4*)M0s[1])[i];
        float4 m2 = ((const float4*)M0s[2])[i];
        float4 m3 = ((const float4*)M0s[3])[i];
        acc0 = fmaf(w.x, m0.x, fmaf(w.y, m0.y, fmaf(w.z, m0.z, fmaf(w.w, m0.w, acc0))));
        acc1 = fmaf(w.x, m1.x, fmaf(w.y, m1.y, fmaf(w.z, m1.z, fmaf(w.w, m1.w, acc1))));
        acc2 = fmaf(w.x, m2.x, fmaf(w.y, m2.y, fmaf(w.z, m2.z, fmaf(w.w, m2.w, acc2))));
        acc3 = fmaf(w.x, m3.x, fmaf(w.y, m3.y, fmaf(w.z, m3.z, fmaf(w.w, m3.w, acc3))));
    }
    g_mgate[(b0 + 0) * KATT_ + k] = rtanh(acc0);
    g_mgate[(b0 + 1) * KATT_ + k] = rtanh(acc1);
    g_mgate[(b0 + 2) * KATT_ + k] = rtanh(acc2);
    g_mgate[(b0 + 3) * KATT_ + k] = rtanh(acc3);
}

// ---------------- K2a: split-K GEMM + tanh-reduce, 2 CTAs/SM ----------------
// CTA = (unit, khalf): T_half[128 k][128 n]; s_part[n] = sum_k whg[k]*tanh(T)
#define A_OFF       0
#define B_OFFS      16384
#define STAGE_BYTES 32768
#define NSTAGE      3
#define WHG_OFF     98304
#define PART_OFF    98816
#define SMEM_K2A    100864

// A chunk [128 m][64 f] fp16 SW128 (rows 128B)
__device__ __forceinline__ void fillA(uint32_t stage, const __half* Wc)
{
    int tid = threadIdx.x;
    #pragma unroll
    for (int it = 0; it < 4; it++) {
        int idx = it * 256 + tid;          // 0..1023
        int m   = idx >> 3;
        int u   = idx & 7;
        cp16(stage + A_OFF + sw128((uint32_t)(m * 128 + u * 16)),
             Wc + (size_t)m * GFS_ + u * 8);
    }
}

// B chunk [64 k(f)][128 n] fp16, rows 256B, 16B-unit XOR by (k&7)
__device__ __forceinline__ void fillB(uint32_t stage, const __half* Xc)
{
    int tid = threadIdx.x;
    #pragma unroll
    for (int it = 0; it < 4; it++) {
        int idx = it * 256 + tid;          // 0..1023
        int k   = idx >> 4;
        int u   = idx & 15;
        cp16(stage + B_OFFS + (uint32_t)(k * 256 + ((u << 4) ^ ((k & 7) << 4))),
             Xc + (size_t)k * NATOMS_ + u * 8);
    }
}

__global__ void __launch_bounds__(256, 2)
gemm_kernel(const float* __restrict__ Wh)
{
    extern __shared__ char sm[];
    uint32_t sb = smem_u32(sm);

    int tid  = threadIdx.x;
    int wid  = tid >> 5;        // 0..7
    int lane = tid & 31;

    int unit  = blockIdx.x >> 1;
    int khalf = blockIdx.x & 1;
    int src   = unit & 1;
    int b     = unit >> 1;

    const __half* W16  = g_w16[src] + (size_t)khalf * 128 * GFS_;
    const __half* Xrow = g_X16[src] + (size_t)b * GFS_ * NATOMS_;

    float* whg  = (float*)(sm + WHG_OFF);    // 128 gated weights for this k-half
    float* part = (float*)(sm + PART_OFF);   // 4 x 128

    if (tid < 128) {
        int k = khalf * 128 + tid;
        whg[tid] = Wh[k] * g_mgate[b * KATT_ + k];
    }

    // warp tile: 32m x 64n; warp grid 4(m) x 2(n)
    int wm = wid >> 1;
    int wn = wid & 1;

    uint32_t aRow = (uint32_t)((wm * 32 + (lane & 15)) * 128);
    uint32_t aCol = (uint32_t)((lane >> 4) * 16);
    int q = lane >> 3;
    int r = lane & 7;
    uint32_t bKpart = (uint32_t)((q & 1) * 8 + r);
    uint32_t bUpart = (uint32_t)(wn * 8 + (q >> 1));   // 16B-unit base (+ jj*2)

    uint32_t stg[NSTAGE] = { sb, sb + STAGE_BYTES, sb + 2 * STAGE_BYTES };

    // prologue: chunks 0,1,2
    fillA(stg[0], W16);       fillB(stg[0], Xrow);                          CP_COMMIT();
    fillA(stg[1], W16 + 64);  fillB(stg[1], Xrow + (size_t)64  * NATOMS_);  CP_COMMIT();
    fillA(stg[2], W16 + 128); fillB(stg[2], Xrow + (size_t)128 * NATOMS_);  CP_COMMIT();

    float acc[2][8][4];
    #pragma unroll
    for (int i = 0; i < 2; i++)
        #pragma unroll
        for (int j = 0; j < 8; j++)
            #pragma unroll
            for (int e = 0; e < 4; e++) acc[i][j][e] = 0.0f;

    #pragma unroll 1
    for (int lc = 0; lc < 8; lc++) {
        if (lc < 6) CP_WAIT2(); else if (lc == 6) CP_WAIT1(); else CP_WAIT0();
        __syncthreads();                     // chunk lc visible block-wide

        int s = lc % 3;
        uint32_t aB = stg[s] + A_OFF;
        uint32_t bB = stg[s] + B_OFFS;

        #pragma unroll
        for (int ks = 0; ks < 4; ks++) {
            uint32_t kOff = (uint32_t)(ks * 32);
            uint32_t a4[8], b4[16];
            #pragma unroll
            for (int i = 0; i < 2; i++)
                ldsm_x4(&a4[i * 4], aB + sw128(aRow + i * 2048 + kOff + aCol));
            uint32_t kRow = (uint32_t)(ks * 16) + bKpart;
            #pragma unroll
            for (int jj = 0; jj < 4; jj++) {
                uint32_t un = bUpart + jj * 2;
                ldsm_x4t(&b4[jj * 4], bB + kRow * 256 + ((un * 16) ^ ((kRow & 7) * 16)));
            }
            #pragma unroll
            for (int i = 0; i < 2; i++)
                #pragma unroll
                for (int j = 0; j < 8; j++)
                    mma_f16(acc[i][j], &a4[i * 4], &b4[j * 2]);
        }

        if (lc < 5) {
            __syncthreads();                 // WAR: all consumed stage lc%3
            int f0 = (lc + 3) * 64;
            fillA(stg[s], W16 + f0);
            fillB(stg[s], Xrow + (size_t)f0 * NATOMS_);
            CP_COMMIT();
        }
    }

    // ---- epilogue: partial logits over this k-half ----
    float p[8][2];
    #pragma unroll
    for (int j = 0; j < 8; j++) { p[j][0] = 0.f; p[j][1] = 0.f; }

    int m0r = wm * 32 + (lane >> 2);
    #pragma unroll
    for (int i = 0; i < 2; i++) {
        float w0 = whg[m0r + i * 16];
        float w1 = whg[m0r + i * 16 + 8];
        #pragma unroll
        for (int j = 0; j < 8; j++) {
            p[j][0] = fmaf(w0, htanh(acc[i][j][0]), p[j][0]);
            p[j][1] = fmaf(w0, htanh(acc[i][j][1]), p[j][1]);
            p[j][0] = fmaf(w1, htanh(acc[i][j][2]), p[j][0]);
            p[j][1] = fmaf(w1, htanh(acc[i][j][3]), p[j][1]);
        }
    }
    #pragma unroll
    for (int off = 4; off <= 16; off <<= 1)
        #pragma unroll
        for (int j = 0; j < 8; j++) {
            p[j][0] += __shfl_xor_sync(0xffffffffu, p[j][0], off);
            p[j][1] += __shfl_xor_sync(0xffffffffu, p[j][1], off);
        }
    if (lane < 4) {
        #pragma unroll
        for (int j = 0; j < 8; j++) {
            int col = wn * 64 + j * 8 + lane * 2;
            part[wm * 128 + col]     = p[j][0];
            part[wm * 128 + col + 1] = p[j][1];
        }
    }
    __syncthreads();

    if (tid < 128) {
        float s = part[tid] + part[128 + tid] + part[256 + tid] + part[384 + tid];
        g_spart[unit][khalf][tid] = s;
    }
}

// ---------------- K2b: combine halves, softmax, alpha + vector outputs ----------------
__global__ void __launch_bounds__(256)
finish_kernel(float* __restrict__ out)
{
    __shared__ __align__(16) float alpha[NATOMS_];

    int tid  = threadIdx.x;
    int wid  = tid >> 5;
    int lane = tid & 31;

    int u   = blockIdx.x;
    int src = u & 1;
    int b   = u >> 1;

    const __half* Xrow = g_X16[src] + (size_t)b * GFS_ * NATOMS_;

    // every warp redundantly reduces all 128 logits (no cross-warp tree)
    {
        float s[4];
        #pragma unroll
        for (int k = 0; k < 4; k++) {
            int n = lane + 32 * k;
            s[k] = g_spart[u][0][n] + g_spart[u][1][n];
        }
        float mx = fmaxf(fmaxf(s[0], s[1]), fmaxf(s[2], s[3]));
        #pragma unroll
        for (int off = 16; off; off >>= 1)
            mx = fmaxf(mx, __shfl_xor_sync(0xffffffffu, mx, off));
        float e[4], sum = 0.f;
        #pragma unroll
        for (int k = 0; k < 4; k++) { e[k] = __expf(s[k] - mx); sum += e[k]; }
        #pragma unroll
        for (int off = 16; off; off >>= 1)
            sum += __shfl_xor_sync(0xffffffffu, sum, off);
        float rs = 1.0f / sum;
        if (wid == 0) {
            #pragma unroll
            for (int k = 0; k < 4; k++) {
                int n = lane + 32 * k;
                float a = e[k] * rs;
                alpha[n] = a;
                out[2 * B_ * GFS_ + src * B_ * NATOMS_ + b * NATOMS_ + n] = a;
            }
        }
    }
    __syncthreads();

    // vector[f] = sum_n alpha[n] * X16[f][n], 2 f per thread
    #pragma unroll
    for (int rep = 0; rep < 2; rep++) {
        int f = tid + rep * 256;
        const uint4* xr = (const uint4*)(Xrow + (size_t)f * NATOMS_);
        float a = 0.0f;
        #pragma unroll
        for (int i = 0; i < 16; i++) {
            uint4 uu = xr[i];
            const float* al = alpha + i * 8;
            float2 p0 = __half22float2(*(const __half2*)&uu.x);
            float2 p1 = __half22float2(*(const __half2*)&uu.y);
            float2 p2 = __half22float2(*(const __half2*)&uu.z);
            float2 p3 = __half22float2(*(const __half2*)&uu.w);
            a = fmaf(p0.x, al[0], a); a = fmaf(p0.y, al[1], a);
            a = fmaf(p1.x, al[2], a); a = fmaf(p1.y, al[3], a);
            a = fmaf(p2.x, al[4], a); a = fmaf(p2.y, al[5], a);
            a = fmaf(p3.x, al[6], a); a = fmaf(p3.y, al[7], a);
        }
        out[src * B_ * GFS_ + b * GFS_ + f] = a;
    }
}

// ---------------- launch ----------------
extern "C" void kernel_launch(void* const* d_in, const int* in_sizes, int n_in,
                              void* d_out, int out_size)
{
    const float* V  = (const float*)d_in[0];
    const float* Q  = (const float*)d_in[1];
    const float* Wm = (const float*)d_in[2];
    const float* Wv = (const float*)d_in[3];
    const float* Wq = (const float*)d_in[4];
    const float* Wh = (const float*)d_in[5];
    float* out = (float*)d_out;

    cudaFuncSetAttribute(gemm_kernel, cudaFuncAttributeMaxDynamicSharedMemorySize, SMEM_K2A);

    prep_kernel<<<256, 1024>>>(Wv, Wq);
    m0_kernel<<<B_ * 4, 256>>>(V, Q);
    gate_kernel<<<B_ / 4, 256>>>(Wm);
    gemm_kernel<<<NUNITS * 2, 256, SMEM_K2A>>>(Wh);
    finish_kernel<<<NUNITS, 256>>>(out);
}